// round 3
// baseline (speedup 1.0000x reference)
#include <cuda_runtime.h>
#include <math.h>

// Problem constants
#define Bn 2
#define Tn 2048
#define Cn 1024
#define Hn 16
#define Dn 64
#define Mrows (Bn * Tn)   // 4096

// Scratch (allocation-free): q, k (RoPE'd), v, attention output y — all in
// [B*T, C] row-major ("[b,t,h,d]") layout so attention reads them with row
// stride C and no transpose pass is needed.
__device__ float g_q[(size_t)Mrows * Cn];
__device__ float g_k[(size_t)Mrows * Cn];
__device__ float g_v[(size_t)Mrows * Cn];
__device__ float g_y[(size_t)Mrows * Cn];

// ---------------------------------------------------------------------------
// GEMM: C[M,N] = A[M,K] @ W[N,K]^T  (both K-major), M=4096, N=K=1024.
// Block tile 64x64, BK=16, 16x16 threads, 4x4 microtile per thread.
// blockIdx.z selects one of up to 3 (W, C) pairs (QKV in one launch).
// Optional fused RoPE epilogue (output tile spans exactly one head: N-tile=64=D).
// ---------------------------------------------------------------------------
__global__ __launch_bounds__(256) void gemm64(
    const float* __restrict__ A,
    const float* __restrict__ W0, const float* __restrict__ W1, const float* __restrict__ W2,
    float* __restrict__ C0, float* __restrict__ C1, float* __restrict__ C2,
    int do_rope)
{
    const int z = blockIdx.z;
    const float* W = (z == 0) ? W0 : ((z == 1) ? W1 : W2);
    float*      Cm = (z == 0) ? C0 : ((z == 1) ? C1 : C2);
    const bool rope = (do_rope != 0) && (z < 2);   // q and k only

    __shared__ float As[16][64];     // [k][m] transposed
    __shared__ float Bs[16][64];     // [k][n] transposed
    __shared__ float Cs[64][68];     // staging for RoPE partner access

    const int tx = threadIdx.x, ty = threadIdx.y;
    const int tid = ty * 16 + tx;
    const int rowBase = blockIdx.y * 64;
    const int colBase = blockIdx.x * 64;

    const int lr = tid >> 2;          // 0..63 : tile row loaded by this thread
    const int lk = (tid & 3) * 4;     // 0,4,8,12 : k offset (float4)

    float acc[4][4];
#pragma unroll
    for (int i = 0; i < 4; i++)
#pragma unroll
        for (int j = 0; j < 4; j++) acc[i][j] = 0.f;

    const float* Aptr = A + (size_t)(rowBase + lr) * Cn + lk;
    const float* Wptr = W + (size_t)(colBase + lr) * Cn + lk;

    for (int k0 = 0; k0 < Cn; k0 += 16) {
        float4 a4 = *(const float4*)(Aptr + k0);
        float4 b4 = *(const float4*)(Wptr + k0);
        As[lk + 0][lr] = a4.x; As[lk + 1][lr] = a4.y;
        As[lk + 2][lr] = a4.z; As[lk + 3][lr] = a4.w;
        Bs[lk + 0][lr] = b4.x; Bs[lk + 1][lr] = b4.y;
        Bs[lk + 2][lr] = b4.z; Bs[lk + 3][lr] = b4.w;
        __syncthreads();
#pragma unroll
        for (int kk = 0; kk < 16; kk++) {
            float4 av = *(const float4*)&As[kk][ty * 4];
            float4 bv = *(const float4*)&Bs[kk][tx * 4];
            float a[4] = {av.x, av.y, av.z, av.w};
            float b[4] = {bv.x, bv.y, bv.z, bv.w};
#pragma unroll
            for (int i = 0; i < 4; i++)
#pragma unroll
                for (int j = 0; j < 4; j++) acc[i][j] += a[i] * b[j];
        }
        __syncthreads();
    }

    if (!rope) {
#pragma unroll
        for (int i = 0; i < 4; i++) {
            float4 o4 = make_float4(acc[i][0], acc[i][1], acc[i][2], acc[i][3]);
            *(float4*)&Cm[(size_t)(rowBase + ty * 4 + i) * Cn + colBase + tx * 4] = o4;
        }
    } else {
        // Stage tile so each thread can reach its rotate_half partner (d ^ 32).
#pragma unroll
        for (int i = 0; i < 4; i++)
#pragma unroll
            for (int j = 0; j < 4; j++) Cs[ty * 4 + i][tx * 4 + j] = acc[i][j];
        __syncthreads();

        const float LOG2_BASE_OVER_HALF = 13.287712379549449f / 32.0f; // log2(10000)/32
#pragma unroll
        for (int i = 0; i < 4; i++) {
            int r = ty * 4 + i;
            int trow = (rowBase + r) & (Tn - 1);   // position within sequence
            float out[4];
#pragma unroll
            for (int jj = 0; jj < 4; jj++) {
                int d = tx * 4 + jj;
                float val  = Cs[r][d];
                float part = Cs[r][d ^ 32];
                float sgn  = (d < 32) ? -1.f : 1.f;
                float freq = exp2f(-(float)(d & 31) * LOG2_BASE_OVER_HALF);
                float th   = (float)trow * freq;
                float sv, cv;
                sincosf(th, &sv, &cv);
                out[jj] = val * cv + sgn * part * sv;
            }
            *(float4*)&Cm[(size_t)(rowBase + r) * Cn + colBase + tx * 4] =
                make_float4(out[0], out[1], out[2], out[3]);
        }
    }
}

// ---------------------------------------------------------------------------
// Flash attention, fp32, online softmax. One block per (q-tile of 32, head, b).
// 128 threads. Q/K/V in [B*T, C] layout (row stride C, head offset h*64).
// smem padded to stride 65 for conflict-free S-phase column access.
// ---------------------------------------------------------------------------
__global__ __launch_bounds__(128) void attn_kernel(
    const float* __restrict__ Qg, const float* __restrict__ Kg,
    const float* __restrict__ Vg, float* __restrict__ Yg)
{
    __shared__ float Qs[32][65], Ks[32][65], Vs[32][65];
    __shared__ float Ps[32][33];
    __shared__ float mrow[32], lrow[32], arow[32];

    const int qi = blockIdx.x, h = blockIdx.y, b = blockIdx.z;
    const int tid = threadIdx.x;

    const size_t qbase = ((size_t)(b * Tn + qi * 32)) * Cn + h * 64;
    for (int i = tid; i < 32 * 64; i += 128) {
        int r = i >> 6, c = i & 63;
        Qs[r][c] = Qg[qbase + (size_t)r * Cn + c] * 0.125f;   // 1/sqrt(64)
    }
    if (tid < 32) { mrow[tid] = -1e30f; lrow[tid] = 0.f; }

    float o[16];
#pragma unroll
    for (int jj = 0; jj < 16; jj++) o[jj] = 0.f;

    const int orow = tid >> 2, olane = tid & 3;        // PV mapping: d = olane + 4*jj
    const int sr = tid >> 2, sc0 = (tid & 3) * 8;      // S mapping: 8 cols per thread

    for (int j = 0; j <= qi; j++) {
        __syncthreads();   // prev-iter Ks/Vs/Ps reads done; Qs/mrow visible on iter 0
        const size_t kb = ((size_t)(b * Tn + j * 32)) * Cn + h * 64;
        for (int i = tid; i < 32 * 64; i += 128) {
            int r = i >> 6, c = i & 63;
            Ks[r][c] = Kg[kb + (size_t)r * Cn + c];
            Vs[r][c] = Vg[kb + (size_t)r * Cn + c];
        }
        __syncthreads();

        // S = Q K^T  (each thread: row sr, 8 columns sc0..sc0+7)
        float acc[8];
#pragma unroll
        for (int i = 0; i < 8; i++) acc[i] = 0.f;
#pragma unroll 16
        for (int kk = 0; kk < 64; kk++) {
            float qv = Qs[sr][kk];
#pragma unroll
            for (int i = 0; i < 8; i++) acc[i] += qv * Ks[sc0 + i][kk];
        }
        const bool diag = (j == qi);
#pragma unroll
        for (int i = 0; i < 8; i++) {
            int c = sc0 + i;
            Ps[sr][c] = (diag && c > sr) ? -1e30f : acc[i];
        }
        __syncthreads();

        // Online softmax (one thread per row)
        if (tid < 32) {
            int r = tid;
            float m_old = mrow[r], mx = m_old;
#pragma unroll
            for (int c = 0; c < 32; c++) mx = fmaxf(mx, Ps[r][c]);
            float alpha = __expf(m_old - mx);
            float s = 0.f;
#pragma unroll
            for (int c = 0; c < 32; c++) {
                float p = __expf(Ps[r][c] - mx);
                Ps[r][c] = p;
                s += p;
            }
            lrow[r] = lrow[r] * alpha + s;
            mrow[r] = mx;
            arow[r] = alpha;
        }
        __syncthreads();

        // O = O*alpha + P V
        float al = arow[orow];
#pragma unroll
        for (int jj = 0; jj < 16; jj++) o[jj] *= al;
#pragma unroll 8
        for (int c = 0; c < 32; c++) {
            float p = Ps[orow][c];
#pragma unroll
            for (int jj = 0; jj < 16; jj++) o[jj] += p * Vs[c][olane + 4 * jj];
        }
    }

    const float invl = 1.0f / lrow[orow];
    const size_t ob = ((size_t)(b * Tn + qi * 32 + orow)) * Cn + h * 64 + olane;
#pragma unroll
    for (int jj = 0; jj < 16; jj++) Yg[ob + 4 * jj] = o[jj] * invl;
}

// ---------------------------------------------------------------------------
extern "C" void kernel_launch(void* const* d_in, const int* in_sizes, int n_in,
                              void* d_out, int out_size)
{
    const float* x  = (const float*)d_in[0];
    const float* Wq = (const float*)d_in[1];
    const float* Wk = (const float*)d_in[2];
    const float* Wv = (const float*)d_in[3];
    const float* Wo = (const float*)d_in[4];
    float* out = (float*)d_out;

    float *q, *k, *v, *y;
    cudaGetSymbolAddress((void**)&q, g_q);
    cudaGetSymbolAddress((void**)&k, g_k);
    cudaGetSymbolAddress((void**)&v, g_v);
    cudaGetSymbolAddress((void**)&y, g_y);

    dim3 tb(16, 16);
    // QKV projections + fused RoPE (q,k) in one launch (z selects matrix)
    gemm64<<<dim3(Cn / 64, Mrows / 64, 3), tb>>>(x, Wq, Wk, Wv, q, k, v, 1);
    // Causal flash attention
    attn_kernel<<<dim3(Tn / 32, Hn, Bn), 128>>>(q, k, v, y);
    // Output projection
    gemm64<<<dim3(Cn / 64, Mrows / 64, 1), tb>>>(y, Wo, Wo, Wo, out, out, out, 0);
}

// round 6
// speedup vs baseline: 1.1198x; 1.1198x over previous
#include <cuda_runtime.h>
#include <math.h>

// Problem constants
#define Bn 2
#define Tn 2048
#define Cn 1024
#define Hn 16
#define Dn 64
#define Mrows (Bn * Tn)   // 4096

// Scratch (allocation-free), all [B*T, C] row-major
__device__ float g_q[(size_t)Mrows * Cn];
__device__ float g_k[(size_t)Mrows * Cn];
__device__ float g_v[(size_t)Mrows * Cn];
__device__ float g_y[(size_t)Mrows * Cn];

// ---------------------------------------------------------------------------
// GEMM: C[M,N] = A[M,K] @ W[N,K]^T, M=4096, N=K=1024.
// 128x128 block tile, BK=16, 256 threads, 8x8 microtile, double-buffered smem.
// blockIdx.z selects one of up to 3 (W,C) pairs. Fused RoPE epilogue for q,k.
// ---------------------------------------------------------------------------
__global__ __launch_bounds__(256, 2) void gemm128(
    const float* __restrict__ A,
    const float* __restrict__ W0, const float* __restrict__ W1, const float* __restrict__ W2,
    float* __restrict__ C0, float* __restrict__ C1, float* __restrict__ C2,
    int do_rope)
{
    __shared__ float As[2][16][128];
    __shared__ float Bs[2][16][128];

    const int z = blockIdx.z;
    const float* W = (z == 0) ? W0 : ((z == 1) ? W1 : W2);
    float*      Cm = (z == 0) ? C0 : ((z == 1) ? C1 : C2);
    const bool rope = (do_rope != 0) && (z < 2);

    const int tid = threadIdx.x;
    const int tx = tid & 15, ty = tid >> 4;
    const int rowBase = blockIdx.y * 128;
    const int colBase = blockIdx.x * 128;

    // Each thread loads 2 float4 per matrix per tile: rows r0 and r0+64, k-quad kq0.
    const int r0  = tid >> 2;
    const int kq0 = (tid & 3) * 4;
    const float* Ap = A + (size_t)(rowBase + r0) * Cn + kq0;
    const float* Wp = W + (size_t)(colBase + r0) * Cn + kq0;

    float acc[8][8];
#pragma unroll
    for (int i = 0; i < 8; i++)
#pragma unroll
        for (int j = 0; j < 8; j++) acc[i][j] = 0.f;

    float4 sa0, sa1, sb0, sb1;

    // Prologue: tile 0 -> buffer 0
    sa0 = *(const float4*)(Ap);
    sa1 = *(const float4*)(Ap + (size_t)64 * Cn);
    sb0 = *(const float4*)(Wp);
    sb1 = *(const float4*)(Wp + (size_t)64 * Cn);
    As[0][kq0 + 0][r0] = sa0.x; As[0][kq0 + 1][r0] = sa0.y;
    As[0][kq0 + 2][r0] = sa0.z; As[0][kq0 + 3][r0] = sa0.w;
    As[0][kq0 + 0][r0 + 64] = sa1.x; As[0][kq0 + 1][r0 + 64] = sa1.y;
    As[0][kq0 + 2][r0 + 64] = sa1.z; As[0][kq0 + 3][r0 + 64] = sa1.w;
    Bs[0][kq0 + 0][r0] = sb0.x; Bs[0][kq0 + 1][r0] = sb0.y;
    Bs[0][kq0 + 2][r0] = sb0.z; Bs[0][kq0 + 3][r0] = sb0.w;
    Bs[0][kq0 + 0][r0 + 64] = sb1.x; Bs[0][kq0 + 1][r0 + 64] = sb1.y;
    Bs[0][kq0 + 2][r0 + 64] = sb1.z; Bs[0][kq0 + 3][r0 + 64] = sb1.w;
    __syncthreads();

    const int NT = Cn / 16;   // 64
#pragma unroll 1
    for (int t = 0; t < NT; t++) {
        const int cur = t & 1;
        if (t < NT - 1) {
            const int k0 = (t + 1) * 16;
            sa0 = *(const float4*)(Ap + k0);
            sa1 = *(const float4*)(Ap + (size_t)64 * Cn + k0);
            sb0 = *(const float4*)(Wp + k0);
            sb1 = *(const float4*)(Wp + (size_t)64 * Cn + k0);
        }
#pragma unroll
        for (int kk = 0; kk < 16; kk++) {
            float4 a0 = *(const float4*)&As[cur][kk][ty * 4];
            float4 a1 = *(const float4*)&As[cur][kk][64 + ty * 4];
            float4 b0 = *(const float4*)&Bs[cur][kk][tx * 4];
            float4 b1 = *(const float4*)&Bs[cur][kk][64 + tx * 4];
            float a[8] = {a0.x, a0.y, a0.z, a0.w, a1.x, a1.y, a1.z, a1.w};
            float b[8] = {b0.x, b0.y, b0.z, b0.w, b1.x, b1.y, b1.z, b1.w};
#pragma unroll
            for (int i = 0; i < 8; i++)
#pragma unroll
                for (int j = 0; j < 8; j++) acc[i][j] += a[i] * b[j];
        }
        if (t < NT - 1) {
            const int nxt = cur ^ 1;
            As[nxt][kq0 + 0][r0] = sa0.x; As[nxt][kq0 + 1][r0] = sa0.y;
            As[nxt][kq0 + 2][r0] = sa0.z; As[nxt][kq0 + 3][r0] = sa0.w;
            As[nxt][kq0 + 0][r0 + 64] = sa1.x; As[nxt][kq0 + 1][r0 + 64] = sa1.y;
            As[nxt][kq0 + 2][r0 + 64] = sa1.z; As[nxt][kq0 + 3][r0 + 64] = sa1.w;
            Bs[nxt][kq0 + 0][r0] = sb0.x; Bs[nxt][kq0 + 1][r0] = sb0.y;
            Bs[nxt][kq0 + 2][r0] = sb0.z; Bs[nxt][kq0 + 3][r0] = sb0.w;
            Bs[nxt][kq0 + 0][r0 + 64] = sb1.x; Bs[nxt][kq0 + 1][r0 + 64] = sb1.y;
            Bs[nxt][kq0 + 2][r0 + 64] = sb1.z; Bs[nxt][kq0 + 3][r0 + 64] = sb1.w;
            __syncthreads();
        }
    }

    if (!rope) {
#pragma unroll
        for (int hm = 0; hm < 2; hm++)
#pragma unroll
            for (int im = 0; im < 4; im++) {
                const int row = rowBase + hm * 64 + ty * 4 + im;
                const int mi = hm * 4 + im;
#pragma unroll
                for (int hn = 0; hn < 2; hn++) {
                    float4 o4 = make_float4(acc[mi][hn * 4 + 0], acc[mi][hn * 4 + 1],
                                            acc[mi][hn * 4 + 2], acc[mi][hn * 4 + 3]);
                    *(float4*)&Cm[(size_t)row * Cn + colBase + hn * 64 + tx * 4] = o4;
                }
            }
    } else {
        // RoPE: partner column c^32 is held by lane tx^8 (same warp) at same (mi, j, hn).
        const float KLOG = 13.287712379549449f / 32.0f;   // log2(10000)/32
#pragma unroll
        for (int hm = 0; hm < 2; hm++)
#pragma unroll
            for (int im = 0; im < 4; im++) {
                const int row = rowBase + hm * 64 + ty * 4 + im;
                const int trow = row & (Tn - 1);
                const int mi = hm * 4 + im;
#pragma unroll
                for (int hn = 0; hn < 2; hn++) {
                    float o[4];
#pragma unroll
                    for (int j = 0; j < 4; j++) {
                        float v = acc[mi][hn * 4 + j];
                        float p = __shfl_xor_sync(0xffffffffu, v, 8);
                        const int d = tx * 4 + j;            // 0..63 within head
                        const float sgn = (d < 32) ? -1.f : 1.f;
                        const float freq = exp2f(-(float)(d & 31) * KLOG);
                        float sv, cv;
                        sincosf((float)trow * freq, &sv, &cv);
                        o[j] = v * cv + sgn * p * sv;
                    }
                    *(float4*)&Cm[(size_t)row * Cn + colBase + hn * 64 + tx * 4] =
                        make_float4(o[0], o[1], o[2], o[3]);
                }
            }
    }
}

// ---------------------------------------------------------------------------
// Flash attention, fp32. q-tile=128, k-tile=64, 256 threads, 8x4 microtiles.
// Q,K stored d-major in smem (float4 frags); V row-major; P row-major.
// Dynamic smem: 104960 B.
// ---------------------------------------------------------------------------
#define QS_STRIDE 132
#define KS_OFF 8448            // 64*132
#define VS_OFF 12800           // + 64*68
#define PS_OFF 17152           // + 64*68
#define MR_OFF 25856           // + 128*68
#define LR_OFF 25984
#define AR_OFF 26112
#define ATTN_SMEM_FLOATS 26240
#define QS(d, m) sm[(d) * QS_STRIDE + (m)]
#define KS(d, n) sm[KS_OFF + (d) * 68 + (n)]
#define VS(c, d) sm[VS_OFF + (c) * 68 + (d)]
#define PS(m, c) sm[PS_OFF + (m) * 68 + (c)]

__global__ __launch_bounds__(256, 2) void attn_kernel(
    const float* __restrict__ Qg, const float* __restrict__ Kg,
    const float* __restrict__ Vg, float* __restrict__ Yg)
{
    extern __shared__ float sm[];
    const int qi = blockIdx.x, h = blockIdx.y, b = blockIdx.z;
    const int tid = threadIdx.x;
    const int tx = tid & 15, ty = tid >> 4;

    // Load Q tile (128 rows x 64 d), transposed + scaled
    const size_t qbase = ((size_t)(b * Tn + qi * 128)) * Cn + h * 64;
#pragma unroll
    for (int it = 0; it < 8; it++) {
        const int p = tid + it * 256;        // 2048 float4s
        const int r = p >> 4, kq = (p & 15) * 4;
        float4 v = *(const float4*)(Qg + qbase + (size_t)r * Cn + kq);
        QS(kq + 0, r) = v.x * 0.125f; QS(kq + 1, r) = v.y * 0.125f;
        QS(kq + 2, r) = v.z * 0.125f; QS(kq + 3, r) = v.w * 0.125f;
    }
    if (tid < 128) { sm[MR_OFF + tid] = -1e30f; sm[LR_OFF + tid] = 0.f; }

    float o[8][4];
#pragma unroll
    for (int i = 0; i < 8; i++)
#pragma unroll
        for (int j = 0; j < 4; j++) o[i][j] = 0.f;

    __syncthreads();

    const int jmax = 2 * qi + 2;
    for (int j = 0; j < jmax; j++) {
        // Load K (transposed) and V (row-major) tiles: 64 rows x 64 d each
        const size_t kb = ((size_t)(b * Tn + j * 64)) * Cn + h * 64;
#pragma unroll
        for (int it = 0; it < 4; it++) {
            const int p = tid + it * 256;    // 1024 float4s
            const int r = p >> 4, kq = (p & 15) * 4;
            float4 kv = *(const float4*)(Kg + kb + (size_t)r * Cn + kq);
            KS(kq + 0, r) = kv.x; KS(kq + 1, r) = kv.y;
            KS(kq + 2, r) = kv.z; KS(kq + 3, r) = kv.w;
            float4 vv = *(const float4*)(Vg + kb + (size_t)r * Cn + kq);
            *(float4*)&VS(r, kq) = vv;
        }
        __syncthreads();

        // S = Q K^T : each thread rows {ty*4+im, 64+ty*4+im}, cols tx*4..+3
        float s[8][4];
#pragma unroll
        for (int i = 0; i < 8; i++)
#pragma unroll
            for (int jj = 0; jj < 4; jj++) s[i][jj] = 0.f;
#pragma unroll 8
        for (int kk = 0; kk < 64; kk++) {
            float4 a0 = *(const float4*)&QS(kk, ty * 4);
            float4 a1 = *(const float4*)&QS(kk, 64 + ty * 4);
            float4 bf = *(const float4*)&KS(kk, tx * 4);
            float a[8] = {a0.x, a0.y, a0.z, a0.w, a1.x, a1.y, a1.z, a1.w};
            float bb[4] = {bf.x, bf.y, bf.z, bf.w};
#pragma unroll
            for (int i = 0; i < 8; i++)
#pragma unroll
                for (int jj = 0; jj < 4; jj++) s[i][jj] += a[i] * bb[jj];
        }
        // Causal mask + store to Ps
#pragma unroll
        for (int hm = 0; hm < 2; hm++)
#pragma unroll
            for (int im = 0; im < 4; im++) {
                const int m = hm * 64 + ty * 4 + im;
                const int mg = qi * 128 + m;
                float v[4];
#pragma unroll
                for (int jc = 0; jc < 4; jc++) {
                    const int cg = j * 64 + tx * 4 + jc;
                    v[jc] = (cg > mg) ? -1e30f : s[hm * 4 + im][jc];
                }
                *(float4*)&PS(m, tx * 4) = make_float4(v[0], v[1], v[2], v[3]);
            }
        __syncthreads();

        // Online softmax: 2 threads per row (32 cols each), combine via shfl
        {
            const int r = tid >> 1;
            const int ch = (tid & 1) * 32;
            const float m_old = sm[MR_OFF + r];
            float mx = m_old;
#pragma unroll
            for (int c = 0; c < 32; c++) mx = fmaxf(mx, PS(r, ch + c));
            mx = fmaxf(mx, __shfl_xor_sync(0xffffffffu, mx, 1));
            const float alpha = __expf(m_old - mx);
            float ssum = 0.f;
#pragma unroll
            for (int c = 0; c < 32; c++) {
                float p = __expf(PS(r, ch + c) - mx);
                PS(r, ch + c) = p;
                ssum += p;
            }
            ssum += __shfl_xor_sync(0xffffffffu, ssum, 1);
            sm[MR_OFF + r] = mx;
            sm[AR_OFF + r] = alpha;
            sm[LR_OFF + r] = sm[LR_OFF + r] * alpha + ssum;
        }
        __syncthreads();

        // O = O*alpha + P V
        float al[8];
#pragma unroll
        for (int hm = 0; hm < 2; hm++)
#pragma unroll
            for (int im = 0; im < 4; im++)
                al[hm * 4 + im] = sm[AR_OFF + hm * 64 + ty * 4 + im];
#pragma unroll
        for (int i = 0; i < 8; i++)
#pragma unroll
            for (int jj = 0; jj < 4; jj++) o[i][jj] *= al[i];
#pragma unroll 8
        for (int c = 0; c < 64; c++) {
            float4 v4 = *(const float4*)&VS(c, tx * 4);
            float pr[8];
#pragma unroll
            for (int hm = 0; hm < 2; hm++)
#pragma unroll
                for (int im = 0; im < 4; im++)
                    pr[hm * 4 + im] = PS(hm * 64 + ty * 4 + im, c);
#pragma unroll
            for (int i = 0; i < 8; i++) {
                o[i][0] += pr[i] * v4.x;
                o[i][1] += pr[i] * v4.y;
                o[i][2] += pr[i] * v4.z;
                o[i][3] += pr[i] * v4.w;
            }
        }
        __syncthreads();   // protect Ks/Vs/Ps before next iteration's loads
    }

    // Write output
#pragma unroll
    for (int hm = 0; hm < 2; hm++)
#pragma unroll
        for (int im = 0; im < 4; im++) {
            const int m = hm * 64 + ty * 4 + im;
            const float il = 1.0f / sm[LR_OFF + m];
            const size_t ob = ((size_t)(b * Tn + qi * 128 + m)) * Cn + h * 64 + tx * 4;
            const int i = hm * 4 + im;
            *(float4*)&Yg[ob] = make_float4(o[i][0] * il, o[i][1] * il,
                                            o[i][2] * il, o[i][3] * il);
        }
}

// ---------------------------------------------------------------------------
extern "C" void kernel_launch(void* const* d_in, const int* in_sizes, int n_in,
                              void* d_out, int out_size)
{
    const float* x  = (const float*)d_in[0];
    const float* Wq = (const float*)d_in[1];
    const float* Wk = (const float*)d_in[2];
    const float* Wv = (const float*)d_in[3];
    const float* Wo = (const float*)d_in[4];
    float* out = (float*)d_out;

    float *q, *k, *v, *y;
    cudaGetSymbolAddress((void**)&q, g_q);
    cudaGetSymbolAddress((void**)&k, g_k);
    cudaGetSymbolAddress((void**)&v, g_v);
    cudaGetSymbolAddress((void**)&y, g_y);

    const int attn_smem = ATTN_SMEM_FLOATS * sizeof(float);   // 104960 B
    cudaFuncSetAttribute(attn_kernel, cudaFuncAttributeMaxDynamicSharedMemorySize, attn_smem);

    // QKV projections + fused RoPE (z selects matrix)
    gemm128<<<dim3(Cn / 128, Mrows / 128, 3), 256>>>(x, Wq, Wk, Wv, q, k, v, 1);
    // Causal flash attention
    attn_kernel<<<dim3(Tn / 128, Hn, Bn), 256, attn_smem>>>(q, k, v, y);
    // Output projection
    gemm128<<<dim3(Cn / 128, Mrows / 128, 1), 256>>>(y, Wo, Wo, Wo, out, out, out, 0);
}

// round 10
// speedup vs baseline: 3.7649x; 3.3621x over previous
#include <cuda_runtime.h>
#include <math.h>
#include <cstdint>

// Problem constants
#define Bn 2
#define Tn 2048
#define Cn 1024
#define Hn 16
#define Dn 64
#define Mrows (Bn * Tn)   // 4096

// Scratch (allocation-free), all [B*T, C] row-major
__device__ float g_q[(size_t)Mrows * Cn];
__device__ float g_k[(size_t)Mrows * Cn];
__device__ float g_v[(size_t)Mrows * Cn];
__device__ float g_y[(size_t)Mrows * Cn];

// ---------------------------------------------------------------------------
// mma.sync tf32 helpers (sm_80+ PTX; works on bare sm_103 target)
// ---------------------------------------------------------------------------
__device__ __forceinline__ float cvt_tf32(float x) {
    float r;
    asm("cvt.rna.tf32.f32 %0, %1;" : "=f"(r) : "f"(x));
    return r;
}

// D(16x8) += A(16x8) * B(8x8); A row-major frag (4 regs), B col-major frag (2 regs)
__device__ __forceinline__ void mma_tf32(float* d, float a0, float a1, float a2, float a3,
                                         float b0, float b1) {
    asm volatile(
        "mma.sync.aligned.m16n8k8.row.col.f32.tf32.tf32.f32 "
        "{%0,%1,%2,%3}, {%4,%5,%6,%7}, {%8,%9}, {%0,%1,%2,%3};"
        : "+f"(d[0]), "+f"(d[1]), "+f"(d[2]), "+f"(d[3])
        : "r"(__float_as_uint(a0)), "r"(__float_as_uint(a1)),
          "r"(__float_as_uint(a2)), "r"(__float_as_uint(a3)),
          "r"(__float_as_uint(b0)), "r"(__float_as_uint(b1)));
}

// ---------------------------------------------------------------------------
// Tensor-core GEMM: C[M,N] = A[M,K] @ W[N,K]^T (tf32 mma.sync, fp32 accum).
// CTA tile 128x128, BK=16 double-buffered, 8 warps (4m x 2n), warp tile 32x64.
// Smem stride 20 floats -> conflict-free fragment LDS.
// Fused RoPE on output fragments for q,k (one warp-N tile == one head).
// ---------------------------------------------------------------------------
__global__ __launch_bounds__(256, 2) void gemm_mma(
    const float* __restrict__ A,
    const float* __restrict__ W0, const float* __restrict__ W1, const float* __restrict__ W2,
    float* __restrict__ C0, float* __restrict__ C1, float* __restrict__ C2,
    int do_rope)
{
    __shared__ float As[2][128][20];
    __shared__ float Bs[2][128][20];

    const int z = blockIdx.z;
    const float* W = (z == 0) ? W0 : ((z == 1) ? W1 : W2);
    float*      Cm = (z == 0) ? C0 : ((z == 1) ? C1 : C2);
    const bool rope = (do_rope != 0) && (z < 2);

    const int tid = threadIdx.x;
    const int wid = tid >> 5, lane = tid & 31;
    const int warpM = wid >> 1, warpN = wid & 1;
    const int lq = lane >> 2, lr4 = lane & 3;      // fragment lane coords
    const int rowBase = blockIdx.y * 128;
    const int colBase = blockIdx.x * 128;

    // Global load mapping: row = tid>>1 (0..127), 2 float4s at cols (tid&1)*8 +{0,4}
    const int glr = tid >> 1;
    const int glc = (tid & 1) * 8;
    const float* Ap = A + (size_t)(rowBase + glr) * Cn + glc;
    const float* Wp = W + (size_t)(colBase + glr) * Cn + glc;

    float acc[2][8][4];
#pragma unroll
    for (int i = 0; i < 2; i++)
#pragma unroll
        for (int j = 0; j < 8; j++)
#pragma unroll
            for (int k = 0; k < 4; k++) acc[i][j][k] = 0.f;

    float4 ra0 = *(const float4*)(Ap);
    float4 ra1 = *(const float4*)(Ap + 4);
    float4 rb0 = *(const float4*)(Wp);
    float4 rb1 = *(const float4*)(Wp + 4);

#pragma unroll 1
    for (int t = 0; t < 64; t++) {
        const int cur = t & 1;
        As[cur][glr][glc + 0] = cvt_tf32(ra0.x); As[cur][glr][glc + 1] = cvt_tf32(ra0.y);
        As[cur][glr][glc + 2] = cvt_tf32(ra0.z); As[cur][glr][glc + 3] = cvt_tf32(ra0.w);
        As[cur][glr][glc + 4] = cvt_tf32(ra1.x); As[cur][glr][glc + 5] = cvt_tf32(ra1.y);
        As[cur][glr][glc + 6] = cvt_tf32(ra1.z); As[cur][glr][glc + 7] = cvt_tf32(ra1.w);
        Bs[cur][glr][glc + 0] = cvt_tf32(rb0.x); Bs[cur][glr][glc + 1] = cvt_tf32(rb0.y);
        Bs[cur][glr][glc + 2] = cvt_tf32(rb0.z); Bs[cur][glr][glc + 3] = cvt_tf32(rb0.w);
        Bs[cur][glr][glc + 4] = cvt_tf32(rb1.x); Bs[cur][glr][glc + 5] = cvt_tf32(rb1.y);
        Bs[cur][glr][glc + 6] = cvt_tf32(rb1.z); Bs[cur][glr][glc + 7] = cvt_tf32(rb1.w);
        if (t < 63) {
            const int k0 = (t + 1) * 16;
            ra0 = *(const float4*)(Ap + k0);
            ra1 = *(const float4*)(Ap + k0 + 4);
            rb0 = *(const float4*)(Wp + k0);
            rb1 = *(const float4*)(Wp + k0 + 4);
        }
        __syncthreads();
#pragma unroll
        for (int ks = 0; ks < 2; ks++) {
            const int k0 = ks * 8;
            float a[2][4];
#pragma unroll
            for (int mf = 0; mf < 2; mf++) {
                const int rb = warpM * 32 + mf * 16;
                a[mf][0] = As[cur][rb + lq][k0 + lr4];
                a[mf][1] = As[cur][rb + lq + 8][k0 + lr4];
                a[mf][2] = As[cur][rb + lq][k0 + lr4 + 4];
                a[mf][3] = As[cur][rb + lq + 8][k0 + lr4 + 4];
            }
#pragma unroll
            for (int nf = 0; nf < 8; nf++) {
                const int cb = warpN * 64 + nf * 8;
                const float b0 = Bs[cur][cb + lq][k0 + lr4];
                const float b1 = Bs[cur][cb + lq][k0 + lr4 + 4];
#pragma unroll
                for (int mf = 0; mf < 2; mf++)
                    mma_tf32(acc[mf][nf], a[mf][0], a[mf][1], a[mf][2], a[mf][3], b0, b1);
            }
        }
        // double-buffered: next iter writes the other buffer; one sync/iter suffices
    }

    // Epilogue: fragment (mf,nf) -> rows {r0, r0+8}, cols col0,col0+1
    const float KLOG = 13.287712379549449f / 32.0f;   // log2(10000)/32
#pragma unroll
    for (int mf = 0; mf < 2; mf++) {
        const int r0 = rowBase + warpM * 32 + mf * 16 + lq;
        if (!rope) {
#pragma unroll
            for (int nf = 0; nf < 8; nf++) {
                const int c0 = colBase + warpN * 64 + nf * 8 + 2 * lr4;
                *(float2*)&Cm[(size_t)r0 * Cn + c0] =
                    make_float2(acc[mf][nf][0], acc[mf][nf][1]);
                *(float2*)&Cm[(size_t)(r0 + 8) * Cn + c0] =
                    make_float2(acc[mf][nf][2], acc[mf][nf][3]);
            }
        } else {
            const int t0 = r0 & (Tn - 1), t1 = (r0 + 8) & (Tn - 1);
#pragma unroll
            for (int nf = 0; nf < 4; nf++) {       // d in [0,32): partner frag nf+4
                const int dlo = nf * 8 + 2 * lr4;  // within head
                const int c0 = colBase + warpN * 64 + dlo;
#pragma unroll
                for (int e = 0; e < 2; e++) {      // the two d's in this frag pair
                    const float freq = exp2f(-(float)(dlo + e) * KLOG);
                    float s0, cth0, s1, cth1;
                    sincosf((float)t0 * freq, &s0, &cth0);
                    sincosf((float)t1 * freq, &s1, &cth1);
                    const float lo0 = acc[mf][nf][e],     hi0 = acc[mf][nf + 4][e];
                    const float lo1 = acc[mf][nf][e + 2], hi1 = acc[mf][nf + 4][e + 2];
                    Cm[(size_t)r0 * Cn + c0 + e]            = lo0 * cth0 - hi0 * s0;
                    Cm[(size_t)r0 * Cn + c0 + e + 32]       = hi0 * cth0 + lo0 * s0;
                    Cm[(size_t)(r0 + 8) * Cn + c0 + e]      = lo1 * cth1 - hi1 * s1;
                    Cm[(size_t)(r0 + 8) * Cn + c0 + e + 32] = hi1 * cth1 + lo1 * s1;
                }
            }
        }
    }
}

// ---------------------------------------------------------------------------
// Flash attention with tf32 mma.sync. q-tile=128, k-tile=64, 256 threads.
// 8 warps (4m x 2n) -> warp tile 32x32 for both S=QK^T and O+=PV.
// Smem strides: Qs 68, Ks 68, Vs 72, Ps 68 (all fragment-LDS conflict-free).
// ---------------------------------------------------------------------------
#define AQS 0
#define AKS 8704              // 128*68
#define AVS 13056             // + 64*68
#define APS 17664             // + 64*72
#define AMR 26368             // + 128*68
#define ALR 26496
#define AAR 26624
#define ATTN_SMEM_FLOATS 26752
#define QSm(m, d) sm[AQS + (m) * 68 + (d)]
#define KSm(n, d) sm[AKS + (n) * 68 + (d)]
#define VSm(c, d) sm[AVS + (c) * 72 + (d)]
#define PSm(m, c) sm[APS + (m) * 68 + (c)]

__global__ __launch_bounds__(256, 2) void attn_kernel(
    const float* __restrict__ Qg, const float* __restrict__ Kg,
    const float* __restrict__ Vg, float* __restrict__ Yg)
{
    extern __shared__ float sm[];
    const int qi = blockIdx.x, h = blockIdx.y, b = blockIdx.z;
    const int tid = threadIdx.x;
    const int wid = tid >> 5, lane = tid & 31;
    const int warpM = wid >> 1, warpN = wid & 1;
    const int lq = lane >> 2, lr4 = lane & 3;
    const int m0 = warpM * 32, n0 = warpN * 32;

    // Load Q (128x64), scaled + tf32
    const size_t qbase = ((size_t)(b * Tn + qi * 128)) * Cn + h * 64;
#pragma unroll
    for (int it = 0; it < 8; it++) {
        const int p = tid + it * 256;
        const int r = p >> 4, c4 = (p & 15) * 4;
        float4 v = *(const float4*)(Qg + qbase + (size_t)r * Cn + c4);
        QSm(r, c4 + 0) = cvt_tf32(v.x * 0.125f);
        QSm(r, c4 + 1) = cvt_tf32(v.y * 0.125f);
        QSm(r, c4 + 2) = cvt_tf32(v.z * 0.125f);
        QSm(r, c4 + 3) = cvt_tf32(v.w * 0.125f);
    }
    if (tid < 128) { sm[AMR + tid] = -1e30f; sm[ALR + tid] = 0.f; }

    float o[2][4][4];
#pragma unroll
    for (int i = 0; i < 2; i++)
#pragma unroll
        for (int j = 0; j < 4; j++)
#pragma unroll
            for (int k = 0; k < 4; k++) o[i][j][k] = 0.f;

    __syncthreads();

    const int jmax = 2 * qi + 2;
    for (int j = 0; j < jmax; j++) {
        // Load K, V tiles (64x64 each)
        const size_t kb = ((size_t)(b * Tn + j * 64)) * Cn + h * 64;
#pragma unroll
        for (int it = 0; it < 4; it++) {
            const int p = tid + it * 256;
            const int r = p >> 4, c4 = (p & 15) * 4;
            float4 kv = *(const float4*)(Kg + kb + (size_t)r * Cn + c4);
            KSm(r, c4 + 0) = cvt_tf32(kv.x); KSm(r, c4 + 1) = cvt_tf32(kv.y);
            KSm(r, c4 + 2) = cvt_tf32(kv.z); KSm(r, c4 + 3) = cvt_tf32(kv.w);
            float4 vv = *(const float4*)(Vg + kb + (size_t)r * Cn + c4);
            VSm(r, c4 + 0) = cvt_tf32(vv.x); VSm(r, c4 + 1) = cvt_tf32(vv.y);
            VSm(r, c4 + 2) = cvt_tf32(vv.z); VSm(r, c4 + 3) = cvt_tf32(vv.w);
        }
        __syncthreads();

        // S = Q K^T (warp tile 32x32)
        float s[2][4][4];
#pragma unroll
        for (int i = 0; i < 2; i++)
#pragma unroll
            for (int jj = 0; jj < 4; jj++)
#pragma unroll
                for (int k = 0; k < 4; k++) s[i][jj][k] = 0.f;
#pragma unroll
        for (int kd = 0; kd < 8; kd++) {
            const int k0 = kd * 8;
            float a[2][4];
#pragma unroll
            for (int mf = 0; mf < 2; mf++) {
                const int rb = m0 + mf * 16;
                a[mf][0] = QSm(rb + lq, k0 + lr4);
                a[mf][1] = QSm(rb + lq + 8, k0 + lr4);
                a[mf][2] = QSm(rb + lq, k0 + lr4 + 4);
                a[mf][3] = QSm(rb + lq + 8, k0 + lr4 + 4);
            }
#pragma unroll
            for (int nf = 0; nf < 4; nf++) {
                const int cb = n0 + nf * 8;
                const float b0 = KSm(cb + lq, k0 + lr4);
                const float b1 = KSm(cb + lq, k0 + lr4 + 4);
#pragma unroll
                for (int mf = 0; mf < 2; mf++)
                    mma_tf32(s[mf][nf], a[mf][0], a[mf][1], a[mf][2], a[mf][3], b0, b1);
            }
        }

        // Mask (diagonal blocks only) + store S to Ps
        const bool need_mask = (j >= 2 * qi);
#pragma unroll
        for (int mf = 0; mf < 2; mf++) {
            const int r0 = m0 + mf * 16 + lq;
#pragma unroll
            for (int nf = 0; nf < 4; nf++) {
                const int c0 = n0 + nf * 8 + 2 * lr4;
                float v0 = s[mf][nf][0], v1 = s[mf][nf][1];
                float v2 = s[mf][nf][2], v3 = s[mf][nf][3];
                if (need_mask) {
                    const int mg0 = qi * 128 + r0, mg1 = mg0 + 8;
                    const int cg0 = j * 64 + c0, cg1 = cg0 + 1;
                    if (cg0 > mg0) v0 = -1e30f;
                    if (cg1 > mg0) v1 = -1e30f;
                    if (cg0 > mg1) v2 = -1e30f;
                    if (cg1 > mg1) v3 = -1e30f;
                }
                *(float2*)&PSm(r0, c0)     = make_float2(v0, v1);
                *(float2*)&PSm(r0 + 8, c0) = make_float2(v2, v3);
            }
        }
        __syncthreads();

        // Online softmax: 2 threads per row
        {
            const int r = tid >> 1;
            const int ch = (tid & 1) * 32;
            const float m_old = sm[AMR + r];
            float mx = m_old;
#pragma unroll
            for (int c = 0; c < 32; c++) mx = fmaxf(mx, PSm(r, ch + c));
            mx = fmaxf(mx, __shfl_xor_sync(0xffffffffu, mx, 1));
            const float alpha = __expf(m_old - mx);
            float ssum = 0.f;
#pragma unroll
            for (int c = 0; c < 32; c++) {
                float p = __expf(PSm(r, ch + c) - mx);
                PSm(r, ch + c) = cvt_tf32(p);
                ssum += p;
            }
            ssum += __shfl_xor_sync(0xffffffffu, ssum, 1);
            sm[AMR + r] = mx;
            sm[AAR + r] = alpha;
            sm[ALR + r] = sm[ALR + r] * alpha + ssum;
        }
        __syncthreads();

        // O = O*alpha + P V (warp tile 32x32 over O[128][64])
        float al[2][2];
#pragma unroll
        for (int mf = 0; mf < 2; mf++) {
            al[mf][0] = sm[AAR + m0 + mf * 16 + lq];
            al[mf][1] = sm[AAR + m0 + mf * 16 + lq + 8];
        }
#pragma unroll
        for (int mf = 0; mf < 2; mf++)
#pragma unroll
            for (int nf = 0; nf < 4; nf++) {
                o[mf][nf][0] *= al[mf][0]; o[mf][nf][1] *= al[mf][0];
                o[mf][nf][2] *= al[mf][1]; o[mf][nf][3] *= al[mf][1];
            }
#pragma unroll
        for (int kc = 0; kc < 8; kc++) {
            const int k0 = kc * 8;
            float a[2][4];
#pragma unroll
            for (int mf = 0; mf < 2; mf++) {
                const int rb = m0 + mf * 16;
                a[mf][0] = PSm(rb + lq, k0 + lr4);
                a[mf][1] = PSm(rb + lq + 8, k0 + lr4);
                a[mf][2] = PSm(rb + lq, k0 + lr4 + 4);
                a[mf][3] = PSm(rb + lq + 8, k0 + lr4 + 4);
            }
#pragma unroll
            for (int nf = 0; nf < 4; nf++) {
                const int cb = n0 + nf * 8;
                const float b0 = VSm(k0 + lr4, cb + lq);
                const float b1 = VSm(k0 + lr4 + 4, cb + lq);
#pragma unroll
                for (int mf = 0; mf < 2; mf++)
                    mma_tf32(o[mf][nf], a[mf][0], a[mf][1], a[mf][2], a[mf][3], b0, b1);
            }
        }
        __syncthreads();   // protect Ks/Vs/Ps before next iteration's loads
    }

    // Final normalize + write
#pragma unroll
    for (int mf = 0; mf < 2; mf++) {
        const int r0 = m0 + mf * 16 + lq;
        const float il0 = 1.0f / sm[ALR + r0];
        const float il1 = 1.0f / sm[ALR + r0 + 8];
#pragma unroll
        for (int nf = 0; nf < 4; nf++) {
            const int c0 = n0 + nf * 8 + 2 * lr4;
            const size_t ob0 = ((size_t)(b * Tn + qi * 128 + r0)) * Cn + h * 64 + c0;
            const size_t ob1 = ((size_t)(b * Tn + qi * 128 + r0 + 8)) * Cn + h * 64 + c0;
            *(float2*)&Yg[ob0] = make_float2(o[mf][nf][0] * il0, o[mf][nf][1] * il0);
            *(float2*)&Yg[ob1] = make_float2(o[mf][nf][2] * il1, o[mf][nf][3] * il1);
        }
    }
}

// ---------------------------------------------------------------------------
extern "C" void kernel_launch(void* const* d_in, const int* in_sizes, int n_in,
                              void* d_out, int out_size)
{
    const float* x  = (const float*)d_in[0];
    const float* Wq = (const float*)d_in[1];
    const float* Wk = (const float*)d_in[2];
    const float* Wv = (const float*)d_in[3];
    const float* Wo = (const float*)d_in[4];
    float* out = (float*)d_out;

    float *q, *k, *v, *y;
    cudaGetSymbolAddress((void**)&q, g_q);
    cudaGetSymbolAddress((void**)&k, g_k);
    cudaGetSymbolAddress((void**)&v, g_v);
    cudaGetSymbolAddress((void**)&y, g_y);

    const int attn_smem = ATTN_SMEM_FLOATS * sizeof(float);   // 107008 B
    cudaFuncSetAttribute(attn_kernel, cudaFuncAttributeMaxDynamicSharedMemorySize, attn_smem);

    // QKV projections + fused RoPE (tf32 mma.sync)
    gemm_mma<<<dim3(Cn / 128, Mrows / 128, 3), 256>>>(x, Wq, Wk, Wv, q, k, v, 1);
    // Causal flash attention (tf32 mma.sync)
    attn_kernel<<<dim3(Tn / 128, Hn, Bn), 256, attn_smem>>>(q, k, v, y);
    // Output projection (tf32 mma.sync)
    gemm_mma<<<dim3(Cn / 128, Mrows / 128, 1), 256>>>(y, Wo, Wo, Wo, out, out, out, 0);
}

// round 11
// speedup vs baseline: 4.1319x; 1.0975x over previous
#include <cuda_runtime.h>
#include <math.h>
#include <cstdint>

// Problem constants
#define Bn 2
#define Tn 2048
#define Cn 1024
#define Hn 16
#define Dn 64
#define Mrows (Bn * Tn)   // 4096

// Scratch (allocation-free), all [B*T, C] row-major
__device__ float g_q[(size_t)Mrows * Cn];
__device__ float g_k[(size_t)Mrows * Cn];
__device__ float g_v[(size_t)Mrows * Cn];
__device__ float g_y[(size_t)Mrows * Cn];
__device__ float g_xr[(size_t)Mrows * Cn];        // tf32-rounded x
__device__ float g_wr[4][(size_t)Cn * Cn];        // tf32-rounded Wq,Wk,Wv,Wo

// ---------------------------------------------------------------------------
// Helpers
// ---------------------------------------------------------------------------
__device__ __forceinline__ float cvt_tf32(float x) {
    float r;
    asm("cvt.rna.tf32.f32 %0, %1;" : "=f"(r) : "f"(x));
    return r;
}
__device__ __forceinline__ uint32_t smem_u32(const void* p) {
    uint32_t a;
    asm("{ .reg .u64 t; cvta.to.shared.u64 t, %1; cvt.u32.u64 %0, t; }" : "=r"(a) : "l"(p));
    return a;
}
__device__ __forceinline__ void cp16(uint32_t dst, const void* src) {
    asm volatile("cp.async.cg.shared.global [%0], [%1], 16;" :: "r"(dst), "l"(src));
}
#define CP_COMMIT() asm volatile("cp.async.commit_group;" ::: "memory")
#define CP_WAIT1()  asm volatile("cp.async.wait_group 1;" ::: "memory")

// D(16x8) += A(16x8) * B(8x8); A row-major frag (4 regs), B col-major frag (2 regs)
__device__ __forceinline__ void mma_tf32(float* d, float a0, float a1, float a2, float a3,
                                         float b0, float b1) {
    asm volatile(
        "mma.sync.aligned.m16n8k8.row.col.f32.tf32.tf32.f32 "
        "{%0,%1,%2,%3}, {%4,%5,%6,%7}, {%8,%9}, {%0,%1,%2,%3};"
        : "+f"(d[0]), "+f"(d[1]), "+f"(d[2]), "+f"(d[3])
        : "r"(__float_as_uint(a0)), "r"(__float_as_uint(a1)),
          "r"(__float_as_uint(a2)), "r"(__float_as_uint(a3)),
          "r"(__float_as_uint(b0)), "r"(__float_as_uint(b1)));
}

// ---------------------------------------------------------------------------
// Prep: round x and the four weight matrices to tf32 (enables raw cp.async)
// ---------------------------------------------------------------------------
__global__ void prep_round(const float* __restrict__ x,
                           const float* __restrict__ wq, const float* __restrict__ wk,
                           const float* __restrict__ wv, const float* __restrict__ wo)
{
    const int seg = blockIdx.y;
    const float* src;
    float* dst;
    int n4;
    if (seg == 0) { src = x;  dst = g_xr;    n4 = Mrows * Cn / 4; }
    else {
        src = (seg == 1) ? wq : (seg == 2) ? wk : (seg == 3) ? wv : wo;
        dst = g_wr[seg - 1];
        n4 = Cn * Cn / 4;
    }
    const int i = blockIdx.x * blockDim.x + threadIdx.x;
    if (i < n4) {
        float4 v = ((const float4*)src)[i];
        v.x = cvt_tf32(v.x); v.y = cvt_tf32(v.y);
        v.z = cvt_tf32(v.z); v.w = cvt_tf32(v.w);
        ((float4*)dst)[i] = v;
    }
}

// ---------------------------------------------------------------------------
// GEMM: C[M,N] = A[M,K] @ W[N,K]^T (tf32 mma.sync, fp32 accum).
// CTA 128x128, BK=16, 3-stage cp.async pipeline, 8 warps (4m x 2n), 32x64 warp tile.
// Smem layout per tile: [128 rows][16 floats], 16B chunk c stored at c ^ ((r>>1)&3).
// Fragment loads proven bank-conflict-free. RoPE fused for q,k; tf32 rounding on
// q,k,v outputs (do_rope launch).
// ---------------------------------------------------------------------------
#define GEMM_SMEM_BYTES 49152   // 2 matrices x 3 stages x 8192 B

__global__ __launch_bounds__(256) void gemm_mma(
    const float* __restrict__ A,
    const float* __restrict__ W0, const float* __restrict__ W1, const float* __restrict__ W2,
    float* __restrict__ C0, float* __restrict__ C1, float* __restrict__ C2,
    int do_rope)
{
    extern __shared__ float sm[];
    float* smA = sm;                 // 3 x 2048 floats
    float* smB = sm + 3 * 2048;
    const uint32_t smbA = smem_u32(smA);
    const uint32_t smbB = smem_u32(smB);

    const int z = blockIdx.z;
    const float* W = (z == 0) ? W0 : ((z == 1) ? W1 : W2);
    float*      Cm = (z == 0) ? C0 : ((z == 1) ? C1 : C2);
    const bool rope = (do_rope != 0) && (z < 2);
    const bool rnd  = (do_rope != 0);

    const int tid = threadIdx.x;
    const int wid = tid >> 5, lane = tid & 31;
    const int warpM = wid >> 1, warpN = wid & 1;
    const int lq = lane >> 2, lr4 = lane & 3;
    const int swl = (lq >> 1) & 3;
    const int rowBase = blockIdx.y * 128;
    const int colBase = blockIdx.x * 128;

    // cp.async mapping: thread -> row cr (0..127), k-half chf; 2 16B chunks per matrix
    const int cr = tid >> 1, chf = tid & 1;
    const float* Ag = A + (size_t)(rowBase + cr) * Cn + chf * 8;
    const float* Wg = W + (size_t)(colBase + cr) * Cn + chf * 8;
    const int swc = (cr >> 1) & 3;
    const uint32_t d0 = (uint32_t)((cr * 16 + (((chf * 2 + 0) ^ swc) << 2)) * 4);
    const uint32_t d1 = (uint32_t)((cr * 16 + (((chf * 2 + 1) ^ swc) << 2)) * 4);

#define G_ISSUE(t, s) do {                                            \
        const float* _ga = Ag + (t) * 16;                             \
        const float* _gw = Wg + (t) * 16;                             \
        const uint32_t _ba = smbA + (s) * 8192;                       \
        const uint32_t _bb = smbB + (s) * 8192;                       \
        cp16(_ba + d0, _ga); cp16(_ba + d1, _ga + 4);                 \
        cp16(_bb + d0, _gw); cp16(_bb + d1, _gw + 4);                 \
    } while (0)

    G_ISSUE(0, 0); CP_COMMIT();
    G_ISSUE(1, 1); CP_COMMIT();

    float acc[2][8][4];
#pragma unroll
    for (int i = 0; i < 2; i++)
#pragma unroll
        for (int j = 0; j < 8; j++)
#pragma unroll
            for (int k = 0; k < 4; k++) acc[i][j][k] = 0.f;

#pragma unroll 1
    for (int t = 0; t < 64; t++) {
        CP_WAIT1();
        __syncthreads();
        if (t + 2 < 64) G_ISSUE(t + 2, (t + 2) % 3);
        CP_COMMIT();

        const float* sA = smA + (t % 3) * 2048;
        const float* sB = smB + (t % 3) * 2048;
#pragma unroll
        for (int ks = 0; ks < 2; ks++) {
            const int c0 = ((ks * 2 + 0) ^ swl) << 2;
            const int c1 = ((ks * 2 + 1) ^ swl) << 2;
            float a[2][4];
#pragma unroll
            for (int mf = 0; mf < 2; mf++) {
                const int r1 = warpM * 32 + mf * 16 + lq;
                const int r2 = r1 + 8;
                a[mf][0] = sA[r1 * 16 + c0 + lr4];
                a[mf][1] = sA[r2 * 16 + c0 + lr4];
                a[mf][2] = sA[r1 * 16 + c1 + lr4];
                a[mf][3] = sA[r2 * 16 + c1 + lr4];
            }
#pragma unroll
            for (int nf = 0; nf < 8; nf++) {
                const int rn = warpN * 64 + nf * 8 + lq;
                const float b0 = sB[rn * 16 + c0 + lr4];
                const float b1 = sB[rn * 16 + c1 + lr4];
#pragma unroll
                for (int mf = 0; mf < 2; mf++)
                    mma_tf32(acc[mf][nf], a[mf][0], a[mf][1], a[mf][2], a[mf][3], b0, b1);
            }
        }
    }

    // Epilogue
    const float KLOG = 13.287712379549449f / 32.0f;   // log2(10000)/32
#pragma unroll
    for (int mf = 0; mf < 2; mf++) {
        const int r0 = rowBase + warpM * 32 + mf * 16 + lq;
        if (!rope) {
#pragma unroll
            for (int nf = 0; nf < 8; nf++) {
                const int c0 = colBase + warpN * 64 + nf * 8 + 2 * lr4;
                float v0 = acc[mf][nf][0], v1 = acc[mf][nf][1];
                float v2 = acc[mf][nf][2], v3 = acc[mf][nf][3];
                if (rnd) { v0 = cvt_tf32(v0); v1 = cvt_tf32(v1);
                           v2 = cvt_tf32(v2); v3 = cvt_tf32(v3); }
                *(float2*)&Cm[(size_t)r0 * Cn + c0]       = make_float2(v0, v1);
                *(float2*)&Cm[(size_t)(r0 + 8) * Cn + c0] = make_float2(v2, v3);
            }
        } else {
            const int t0 = r0 & (Tn - 1), t1 = (r0 + 8) & (Tn - 1);
#pragma unroll
            for (int nf = 0; nf < 4; nf++) {       // d in [0,32): partner frag nf+4
                const int dlo = nf * 8 + 2 * lr4;
                const int c0 = colBase + warpN * 64 + dlo;
#pragma unroll
                for (int e = 0; e < 2; e++) {
                    const float freq = exp2f(-(float)(dlo + e) * KLOG);
                    float s0, cth0, s1, cth1;
                    sincosf((float)t0 * freq, &s0, &cth0);
                    sincosf((float)t1 * freq, &s1, &cth1);
                    const float lo0 = acc[mf][nf][e],     hi0 = acc[mf][nf + 4][e];
                    const float lo1 = acc[mf][nf][e + 2], hi1 = acc[mf][nf + 4][e + 2];
                    Cm[(size_t)r0 * Cn + c0 + e]            = cvt_tf32(lo0 * cth0 - hi0 * s0);
                    Cm[(size_t)r0 * Cn + c0 + e + 32]       = cvt_tf32(hi0 * cth0 + lo0 * s0);
                    Cm[(size_t)(r0 + 8) * Cn + c0 + e]      = cvt_tf32(lo1 * cth1 - hi1 * s1);
                    Cm[(size_t)(r0 + 8) * Cn + c0 + e + 32] = cvt_tf32(hi1 * cth1 + lo1 * s1);
                }
            }
        }
    }
#undef G_ISSUE
}

// ---------------------------------------------------------------------------
// Flash attention, tf32 mma.sync + 3-stage cp.async K/V pipeline.
// q-tile=128, k-tile=64, 256 threads, warp tile 32x32 (4m x 2n warps).
// Q/K/V in swizzled [row][64] layout via cp.async; P in stride-68 scalar smem.
// Smem floats: Q 8192 | K 3x4096 | V 3x4096 | P 8704 | stats 384 = 41856.
// ---------------------------------------------------------------------------
#define AQ 0
#define AK 8192
#define AV 20480
#define AP 32768
#define AM 41472
#define AL 41600
#define AA 41728
#define ATTN_SMEM_FLOATS 41856
#define PSm(m, c) sm[AP + (m) * 68 + (c)]

__global__ __launch_bounds__(256) void attn_kernel(
    const float* __restrict__ Qg, const float* __restrict__ Kg,
    const float* __restrict__ Vg, float* __restrict__ Yg)
{
    extern __shared__ float sm[];
    const uint32_t smb = smem_u32(sm);
    const int qi = (int)(gridDim.x - 1 - blockIdx.x);   // long tiles first
    const int h = blockIdx.y, b = blockIdx.z;
    const int tid = threadIdx.x;
    const int wid = tid >> 5, lane = tid & 31;
    const int warpM = wid >> 2, warpN = wid & 3;        // 2m x 4n? no: 4m x 2n below
    // Re-derive: 8 warps as 4 (M) x 2 (N)
    const int wM = wid >> 1, wN = wid & 1;
    const int lq = lane >> 2, lr4 = lane & 3;
    const int m0 = wM * 32, n0 = wN * 32;
    (void)warpM; (void)warpN;

    // cp.async mappings
    const int qr = tid >> 1, qci = tid & 1;             // Q: 128 rows x 2 col-halves
    const float* Qp = Qg + (size_t)(b * Tn + qi * 128 + qr) * Cn + h * 64 + qci * 32;
    const int kr = tid >> 2, kci = tid & 3;             // K/V: 64 rows x 4 col-quarters
    const float* Kp = Kg + (size_t)(b * Tn + kr) * Cn + h * 64 + kci * 16;
    const float* Vp = Vg + (size_t)(b * Tn + kr) * Cn + h * 64 + kci * 16;

#define KV_ISSUE(j, s) do {                                                     \
        const float* _kp = Kp + (size_t)((j) * 64) * Cn;                        \
        const float* _vp = Vp + (size_t)((j) * 64) * Cn;                        \
        const uint32_t _bk = smb + (AK + (s) * 4096) * 4;                       \
        const uint32_t _bv = smb + (AV + (s) * 4096) * 4;                       \
        _Pragma("unroll")                                                       \
        for (int _i = 0; _i < 4; _i++) {                                        \
            const int _c = kci * 4 + _i;                                        \
            const uint32_t _off = (uint32_t)((kr * 64 + ((_c ^ (kr & 7)) << 2)) * 4); \
            cp16(_bk + _off, _kp + _i * 4);                                     \
            cp16(_bv + _off, _vp + _i * 4);                                     \
        }                                                                       \
    } while (0)

    // Prologue: group0 = Q + KV(0); group1 = KV(1)
#pragma unroll
    for (int i = 0; i < 8; i++) {
        const int c = qci * 8 + i;
        cp16(smb + (uint32_t)((qr * 64 + ((c ^ (qr & 7)) << 2)) * 4), Qp + i * 4);
    }
    KV_ISSUE(0, 0); CP_COMMIT();
    KV_ISSUE(1, 1); CP_COMMIT();

    if (tid < 128) { sm[AM + tid] = -1e30f; sm[AL + tid] = 0.f; }

    float o[2][4][4];
#pragma unroll
    for (int i = 0; i < 2; i++)
#pragma unroll
        for (int j = 0; j < 4; j++)
#pragma unroll
            for (int k = 0; k < 4; k++) o[i][j][k] = 0.f;

    const int jmax = 2 * qi + 2;
#pragma unroll 1
    for (int j = 0; j < jmax; j++) {
        CP_WAIT1();
        __syncthreads();
        if (j + 2 < jmax) KV_ISSUE(j + 2, (j + 2) % 3);
        CP_COMMIT();

        const float* sQ = sm + AQ;
        const float* sK = sm + AK + (j % 3) * 4096;
        const float* sV = sm + AV + (j % 3) * 4096;

        // ---- S = Q K^T ----
        float s[2][4][4];
#pragma unroll
        for (int i = 0; i < 2; i++)
#pragma unroll
            for (int jj = 0; jj < 4; jj++)
#pragma unroll
                for (int k = 0; k < 4; k++) s[i][jj][k] = 0.f;
#pragma unroll
        for (int kd = 0; kd < 8; kd++) {
            const int c0 = ((kd * 2 + 0) ^ lq) << 2;
            const int c1 = ((kd * 2 + 1) ^ lq) << 2;
            float a[2][4];
#pragma unroll
            for (int mf = 0; mf < 2; mf++) {
                const int r1 = m0 + mf * 16 + lq;
                const int r2 = r1 + 8;
                a[mf][0] = sQ[r1 * 64 + c0 + lr4];
                a[mf][1] = sQ[r2 * 64 + c0 + lr4];
                a[mf][2] = sQ[r1 * 64 + c1 + lr4];
                a[mf][3] = sQ[r2 * 64 + c1 + lr4];
            }
#pragma unroll
            for (int nf = 0; nf < 4; nf++) {
                const int rn = n0 + nf * 8 + lq;
                const float b0 = sK[rn * 64 + c0 + lr4];
                const float b1 = sK[rn * 64 + c1 + lr4];
#pragma unroll
                for (int mf = 0; mf < 2; mf++)
                    mma_tf32(s[mf][nf], a[mf][0], a[mf][1], a[mf][2], a[mf][3], b0, b1);
            }
        }

        // ---- scale + mask + store S to P ----
        const bool need_mask = (j >= 2 * qi);
#pragma unroll
        for (int mf = 0; mf < 2; mf++) {
            const int r0 = m0 + mf * 16 + lq;
#pragma unroll
            for (int nf = 0; nf < 4; nf++) {
                const int c0 = n0 + nf * 8 + 2 * lr4;
                float v0 = s[mf][nf][0] * 0.125f, v1 = s[mf][nf][1] * 0.125f;
                float v2 = s[mf][nf][2] * 0.125f, v3 = s[mf][nf][3] * 0.125f;
                if (need_mask) {
                    const int mg0 = qi * 128 + r0, mg1 = mg0 + 8;
                    const int cg0 = j * 64 + c0, cg1 = cg0 + 1;
                    if (cg0 > mg0) v0 = -1e30f;
                    if (cg1 > mg0) v1 = -1e30f;
                    if (cg0 > mg1) v2 = -1e30f;
                    if (cg1 > mg1) v3 = -1e30f;
                }
                *(float2*)&PSm(r0, c0)     = make_float2(v0, v1);
                *(float2*)&PSm(r0 + 8, c0) = make_float2(v2, v3);
            }
        }
        __syncthreads();

        // ---- online softmax: 2 threads per row ----
        {
            const int r = tid >> 1;
            const int ch = (tid & 1) * 32;
            const float m_old = sm[AM + r];
            float mx = m_old;
#pragma unroll
            for (int c = 0; c < 32; c++) mx = fmaxf(mx, PSm(r, ch + c));
            mx = fmaxf(mx, __shfl_xor_sync(0xffffffffu, mx, 1));
            const float alpha = __expf(m_old - mx);
            float ssum = 0.f;
#pragma unroll
            for (int c = 0; c < 32; c++) {
                float p = __expf(PSm(r, ch + c) - mx);
                PSm(r, ch + c) = cvt_tf32(p);
                ssum += p;
            }
            ssum += __shfl_xor_sync(0xffffffffu, ssum, 1);
            sm[AM + r] = mx;
            sm[AA + r] = alpha;
            sm[AL + r] = sm[AL + r] * alpha + ssum;
        }
        __syncthreads();

        // ---- O = O*alpha + P V ----
        float al[2][2];
#pragma unroll
        for (int mf = 0; mf < 2; mf++) {
            al[mf][0] = sm[AA + m0 + mf * 16 + lq];
            al[mf][1] = sm[AA + m0 + mf * 16 + lq + 8];
        }
#pragma unroll
        for (int mf = 0; mf < 2; mf++)
#pragma unroll
            for (int nf = 0; nf < 4; nf++) {
                o[mf][nf][0] *= al[mf][0]; o[mf][nf][1] *= al[mf][0];
                o[mf][nf][2] *= al[mf][1]; o[mf][nf][3] *= al[mf][1];
            }
#pragma unroll
        for (int kc = 0; kc < 8; kc++) {
            const int k0 = kc * 8;
            float a[2][4];
#pragma unroll
            for (int mf = 0; mf < 2; mf++) {
                const int rb = m0 + mf * 16;
                a[mf][0] = PSm(rb + lq, k0 + lr4);
                a[mf][1] = PSm(rb + lq + 8, k0 + lr4);
                a[mf][2] = PSm(rb + lq, k0 + lr4 + 4);
                a[mf][3] = PSm(rb + lq + 8, k0 + lr4 + 4);
            }
#pragma unroll
            for (int nf = 0; nf < 4; nf++) {
                const int cbl = n0 + nf * 8 + lq;
                const float b0 = sV[(k0 + lr4) * 64 +
                                   (((cbl >> 2) ^ lr4) << 2) + (cbl & 3)];
                const float b1 = sV[(k0 + lr4 + 4) * 64 +
                                   (((cbl >> 2) ^ (lr4 + 4)) << 2) + (cbl & 3)];
#pragma unroll
                for (int mf = 0; mf < 2; mf++)
                    mma_tf32(o[mf][nf], a[mf][0], a[mf][1], a[mf][2], a[mf][3], b0, b1);
            }
        }
        // next-iteration top sync protects P/V reuse
    }

    // ---- normalize + write (tf32-rounded for the out-proj cp.async) ----
#pragma unroll
    for (int mf = 0; mf < 2; mf++) {
        const int r0 = m0 + mf * 16 + lq;
        const float il0 = 1.0f / sm[AL + r0];
        const float il1 = 1.0f / sm[AL + r0 + 8];
#pragma unroll
        for (int nf = 0; nf < 4; nf++) {
            const int c0 = n0 + nf * 8 + 2 * lr4;
            const size_t ob0 = ((size_t)(b * Tn + qi * 128 + r0)) * Cn + h * 64 + c0;
            const size_t ob1 = ((size_t)(b * Tn + qi * 128 + r0 + 8)) * Cn + h * 64 + c0;
            *(float2*)&Yg[ob0] = make_float2(cvt_tf32(o[mf][nf][0] * il0),
                                             cvt_tf32(o[mf][nf][1] * il0));
            *(float2*)&Yg[ob1] = make_float2(cvt_tf32(o[mf][nf][2] * il1),
                                             cvt_tf32(o[mf][nf][3] * il1));
        }
    }
#undef KV_ISSUE
}

// ---------------------------------------------------------------------------
extern "C" void kernel_launch(void* const* d_in, const int* in_sizes, int n_in,
                              void* d_out, int out_size)
{
    const float* x  = (const float*)d_in[0];
    const float* Wq = (const float*)d_in[1];
    const float* Wk = (const float*)d_in[2];
    const float* Wv = (const float*)d_in[3];
    const float* Wo = (const float*)d_in[4];
    float* out = (float*)d_out;

    float *q, *k, *v, *y, *xr, *wr;
    cudaGetSymbolAddress((void**)&q,  g_q);
    cudaGetSymbolAddress((void**)&k,  g_k);
    cudaGetSymbolAddress((void**)&v,  g_v);
    cudaGetSymbolAddress((void**)&y,  g_y);
    cudaGetSymbolAddress((void**)&xr, g_xr);
    cudaGetSymbolAddress((void**)&wr, g_wr);
    float* wq_r = wr;
    float* wk_r = wr + (size_t)Cn * Cn;
    float* wv_r = wr + (size_t)2 * Cn * Cn;
    float* wo_r = wr + (size_t)3 * Cn * Cn;

    const int attn_smem = ATTN_SMEM_FLOATS * sizeof(float);   // 167424 B
    cudaFuncSetAttribute(attn_kernel, cudaFuncAttributeMaxDynamicSharedMemorySize, attn_smem);
    cudaFuncSetAttribute(gemm_mma, cudaFuncAttributeMaxDynamicSharedMemorySize, GEMM_SMEM_BYTES);

    // 0) round inputs to tf32 once
    prep_round<<<dim3(4096, 5), 256>>>(x, Wq, Wk, Wv, Wo);
    // 1) QKV projections + fused RoPE
    gemm_mma<<<dim3(Cn / 128, Mrows / 128, 3), 256, GEMM_SMEM_BYTES>>>(
        xr, wq_r, wk_r, wv_r, q, k, v, 1);
    // 2) causal flash attention
    attn_kernel<<<dim3(Tn / 128, Hn, Bn), 256, attn_smem>>>(q, k, v, y);
    // 3) output projection
    gemm_mma<<<dim3(Cn / 128, Mrows / 128, 1), 256, GEMM_SMEM_BYTES>>>(
        y, wo_r, wo_r, wo_r, out, out, out, 0);
}